// round 2
// baseline (speedup 1.0000x reference)
#include <cuda_runtime.h>
#include <math.h>

#define TT 512
#define BBATCH 4
#define CC 256
#define NN 2048
#define DD 65536
#define NE 64
#define ROUT 256
#define DECAYv 0.999f
#define GAMv ((float)((1.0 - 0.999) / 2048.0))
#define COMMITv 0.25f

// ---------------- device scratch (no allocations allowed) ----------------
__device__ float g_M[CC*CC];        // W^T W
__device__ float g_G[NE*CC];        // Cents @ W
__device__ float g_A[NE*CC];        // resp^T X
__device__ float g_H[NE*NE];        // Cnew Cnew^T
__device__ float g_cnorm[NE], g_bc[NE], g_s[NE];
__device__ float g_Wtb[CC];
__device__ float g_bb;
__device__ float g_acc[3];          // sum qnorm, sum cross, sum quad
__device__ float g_pw1T[CC*CC];
__device__ float g_XM[NN*CC];
__device__ float g_Y[NN*CC];
__device__ float g_xG[NN*NE];
__device__ float g_qnorm[NN], g_xWtb[NN];
__device__ float g_resp[NN*NE];
__device__ float g_Cnew[NE*DD];     // 16.7 MB

// ---------------- zero accumulators ----------------
__global__ void k_zero() {
    int i = blockIdx.x * blockDim.x + threadIdx.x;
    if (i < CC*CC) g_M[i] = 0.f;
    if (i < NE*CC) { g_G[i] = 0.f; g_A[i] = 0.f; }
    if (i < NE*NE) g_H[i] = 0.f;
    if (i < CC)    g_Wtb[i] = 0.f;
    if (i < NE)    { g_cnorm[i] = 0.f; g_bc[i] = 0.f; g_s[i] = 0.f; }
    if (i == 0)    { g_bb = 0.f; g_acc[0] = 0.f; g_acc[1] = 0.f; g_acc[2] = 0.f; }
}

// ---------------- M = W^T W   (split-K, 64x64 tiles, atomics) ----------------
__global__ void k_gram(const float* __restrict__ W) {
    __shared__ float sa[16][64];
    __shared__ float sb[16][64];
    int tid = threadIdx.x;
    int i0 = blockIdx.x * 64, j0 = blockIdx.y * 64;
    int d0 = blockIdx.z * 2048;
    int ty = tid >> 4, tx = tid & 15;
    float acc[4][4];
#pragma unroll
    for (int r = 0; r < 4; r++)
#pragma unroll
        for (int c = 0; c < 4; c++) acc[r][c] = 0.f;

    for (int ks = 0; ks < 2048; ks += 16) {
#pragma unroll
        for (int l = 0; l < 4; l++) {
            int idx = tid + l * 256;
            int dd = idx >> 6, cc2 = idx & 63;
            const float* row = W + (size_t)(d0 + ks + dd) * CC;
            sa[dd][cc2] = row[i0 + cc2];
            sb[dd][cc2] = row[j0 + cc2];
        }
        __syncthreads();
#pragma unroll
        for (int dd = 0; dd < 16; dd++) {
            float a[4], bv[4];
#pragma unroll
            for (int r = 0; r < 4; r++) a[r] = sa[dd][ty*4 + r];
#pragma unroll
            for (int c = 0; c < 4; c++) bv[c] = sb[dd][tx*4 + c];
#pragma unroll
            for (int r = 0; r < 4; r++)
#pragma unroll
                for (int c = 0; c < 4; c++) acc[r][c] += a[r] * bv[c];
        }
        __syncthreads();
    }
#pragma unroll
    for (int r = 0; r < 4; r++)
#pragma unroll
        for (int c = 0; c < 4; c++)
            atomicAdd(&g_M[(i0 + ty*4 + r) * CC + (j0 + tx*4 + c)], acc[r][c]);
}

// ---------------- G = Cents @ W, plus cnorm, bc, Wtb, bb ----------------
__global__ void k_centW(const float* __restrict__ W, const float* __restrict__ cents,
                        const float* __restrict__ bvec) {
    __shared__ float cs[NE][65];
    __shared__ float bs[64];
    int tid = threadIdx.x;
    int d0 = blockIdx.x * 512;
    float accG[NE];
#pragma unroll
    for (int e = 0; e < NE; e++) accG[e] = 0.f;
    float accWtb = 0.f, accCN = 0.f, accBC = 0.f, accBB = 0.f;

    for (int ds = 0; ds < 512; ds += 64) {
        int dbase = d0 + ds;
#pragma unroll
        for (int l = 0; l < 16; l++) {
            int idx = tid + l * 256;
            int e = idx >> 6, dd = idx & 63;
            cs[e][dd] = cents[(size_t)e * DD + dbase + dd];
        }
        if (tid < 64) bs[tid] = bvec[dbase + tid];
        __syncthreads();

        for (int dd = 0; dd < 64; dd++) {
            float w = W[(size_t)(dbase + dd) * CC + tid];
            accWtb += bs[dd] * w;
#pragma unroll
            for (int e = 0; e < NE; e++) accG[e] += cs[e][dd] * w;
        }
        if (tid < NE) {
            float cn = 0.f, bc = 0.f;
            for (int dd = 0; dd < 64; dd++) { float c = cs[tid][dd]; cn += c*c; bc += c*bs[dd]; }
            accCN += cn; accBC += bc;
        }
        if (tid == 64) {
            float s = 0.f;
            for (int dd = 0; dd < 64; dd++) s += bs[dd]*bs[dd];
            accBB += s;
        }
        __syncthreads();
    }
#pragma unroll
    for (int e = 0; e < NE; e++) atomicAdd(&g_G[e * CC + tid], accG[e]);
    atomicAdd(&g_Wtb[tid], accWtb);
    if (tid < NE) { atomicAdd(&g_cnorm[tid], accCN); atomicAdd(&g_bc[tid], accBC); }
    if (tid == 64) atomicAdd(&g_bb, accBB);
}

// ---------------- transpose pw1 ----------------
__global__ void k_pw1T(const float* __restrict__ pw1) {
    int c = blockIdx.x, k = threadIdx.x;
    g_pw1T[c * CC + k] = pw1[k * CC + c];
}

// ---------------- XM = X@M, Y = X@pw1^T, xG = X@G^T, qnorm, xWtb ----------------
__global__ void k_xsmall(const float* __restrict__ x) {
    __shared__ float xs[8][CC];
    __shared__ float red[256];
    int tid = threadIdx.x;
    int n0 = blockIdx.x * 8;
#pragma unroll
    for (int l = 0; l < 8; l++) {
        int idx = tid + l * 256;
        xs[idx >> 8][idx & 255] = x[(size_t)n0 * CC + idx];
    }
    __syncthreads();

    float acc[8], accY[8];
#pragma unroll
    for (int t = 0; t < 8; t++) { acc[t] = 0.f; accY[t] = 0.f; }
    for (int c = 0; c < CC; c++) {
        float m = g_M[c * CC + tid];
        float p = g_pw1T[c * CC + tid];
#pragma unroll
        for (int t = 0; t < 8; t++) { acc[t] += xs[t][c] * m; accY[t] += xs[t][c] * p; }
    }
#pragma unroll
    for (int t = 0; t < 8; t++) {
        g_XM[(size_t)(n0 + t) * CC + tid] = acc[t];
        g_Y[(size_t)(n0 + t) * CC + tid]  = accY[t];
    }

    float wtb = g_Wtb[tid];
    float bb = g_bb;
    for (int t = 0; t < 8; t++) {
        // qdot = sum_j XM*x
        red[tid] = acc[t] * xs[t][tid];
        __syncthreads();
        for (int s = 128; s >= 1; s >>= 1) { if (tid < s) red[tid] += red[tid + s]; __syncthreads(); }
        float qdot = red[0]; __syncthreads();
        // xwtb = sum_j x*Wtb
        red[tid] = xs[t][tid] * wtb;
        __syncthreads();
        for (int s = 128; s >= 1; s >>= 1) { if (tid < s) red[tid] += red[tid + s]; __syncthreads(); }
        float xwtb = red[0]; __syncthreads();
        if (tid == 0) {
            g_qnorm[n0 + t] = qdot + 2.f * xwtb + bb;
            g_xWtb[n0 + t]  = xwtb;
        }
    }

    // xG: thread = (e, part p of 4)
    int e = tid & 63, p = tid >> 6;
    for (int t = 0; t < 8; t++) {
        float sum = 0.f;
        int cbase = p * 64;
        for (int c = 0; c < 64; c++) sum += xs[t][cbase + c] * g_G[e * CC + cbase + c];
        red[tid] = sum;
        __syncthreads();
        if (p == 0) g_xG[(size_t)(n0 + t) * NE + e] = red[e] + red[64 + e] + red[128 + e] + red[192 + e];
        __syncthreads();
    }
}

// ---------------- resp = softmax((-d2 + gumbel)/tau) ----------------
__global__ void k_resp(const float* __restrict__ u) {
    __shared__ float red[64];
    int n = blockIdx.x, e = threadIdx.x;
    float d2 = g_qnorm[n] + g_cnorm[e] - 2.f * (g_xG[(size_t)n * NE + e] + g_bc[e]);
    float g = -logf(-logf(u[(size_t)n * NE + e]));
    float logit = -d2 + g;   // TAU = 1
    red[e] = logit; __syncthreads();
    for (int s = 32; s >= 1; s >>= 1) { if (e < s) red[e] = fmaxf(red[e], red[e + s]); __syncthreads(); }
    float mx = red[0]; __syncthreads();
    float ex = expf(logit - mx);
    red[e] = ex; __syncthreads();
    for (int s = 32; s >= 1; s >>= 1) { if (e < s) red[e] += red[e + s]; __syncthreads(); }
    g_resp[(size_t)n * NE + e] = ex / red[0];
}

// ---------------- A = resp^T X, s = colsum(resp) ----------------
__global__ void k_A(const float* __restrict__ x) {
    __shared__ float rs[32][NE + 1];
    int tid = threadIdx.x;
    int n0 = blockIdx.x * 32;
#pragma unroll
    for (int l = 0; l < 8; l++) {
        int idx = tid + l * 256;
        rs[idx >> 6][idx & 63] = g_resp[(size_t)(n0 + (idx >> 6)) * NE + (idx & 63)];
    }
    __syncthreads();
    float acc[NE];
#pragma unroll
    for (int e = 0; e < NE; e++) acc[e] = 0.f;
    for (int t = 0; t < 32; t++) {
        float xv = x[(size_t)(n0 + t) * CC + tid];
#pragma unroll
        for (int e = 0; e < NE; e++) acc[e] += rs[t][e] * xv;
    }
#pragma unroll
    for (int e = 0; e < NE; e++) atomicAdd(&g_A[e * CC + tid], acc[e]);
    if (tid < NE) {
        float s = 0.f;
        for (int t = 0; t < 32; t++) s += rs[t][tid];
        atomicAdd(&g_s[tid], s);
    }
}

// ---------------- Cnew = decay*Cents + gam*(A@W^T + s b^T) ----------------
__global__ void k_cnew(const float* __restrict__ W, const float* __restrict__ cents,
                       const float* __restrict__ bvec) {
    __shared__ float Ws[64][65];
    __shared__ float As[64][65];
    int tid = threadIdx.x;
    int d0 = blockIdx.x * 64;
    int te = tid >> 4, td = tid & 15;
    float acc[4][4];
#pragma unroll
    for (int r = 0; r < 4; r++)
#pragma unroll
        for (int q = 0; q < 4; q++) acc[r][q] = 0.f;

    for (int kc = 0; kc < CC; kc += 64) {
#pragma unroll
        for (int l = 0; l < 16; l++) {
            int idx = tid + l * 256;
            int r2 = idx >> 6, c2 = idx & 63;
            Ws[r2][c2] = W[(size_t)(d0 + r2) * CC + kc + c2];
            As[r2][c2] = g_A[r2 * CC + kc + c2];
        }
        __syncthreads();
        for (int kk = 0; kk < 64; kk++) {
            float a[4], wv[4];
#pragma unroll
            for (int r = 0; r < 4; r++) a[r] = As[te*4 + r][kk];
#pragma unroll
            for (int q = 0; q < 4; q++) wv[q] = Ws[td*4 + q][kk];
#pragma unroll
            for (int r = 0; r < 4; r++)
#pragma unroll
                for (int q = 0; q < 4; q++) acc[r][q] += a[r] * wv[q];
        }
        __syncthreads();
    }
#pragma unroll
    for (int r = 0; r < 4; r++) {
        int e = te*4 + r;
        float se = g_s[e];
#pragma unroll
        for (int q = 0; q < 4; q++) {
            int d = d0 + td*4 + q;
            g_Cnew[(size_t)e * DD + d] =
                DECAYv * cents[(size_t)e * DD + d] + GAMv * (acc[r][q] + se * bvec[d]);
        }
    }
}

// ---------------- H = Cnew Cnew^T ----------------
__global__ void k_H() {
    __shared__ float cn[NE][129];
    int tid = threadIdx.x;
    int e1 = tid & 63, g2 = tid >> 6;
    float acc[16];
#pragma unroll
    for (int i = 0; i < 16; i++) acc[i] = 0.f;
    int d0 = blockIdx.x * 512;
    for (int ds = 0; ds < 512; ds += 128) {
#pragma unroll
        for (int l = 0; l < 32; l++) {
            int idx = tid + l * 256;
            cn[idx >> 7][idx & 127] = g_Cnew[(size_t)(idx >> 7) * DD + d0 + ds + (idx & 127)];
        }
        __syncthreads();
        for (int dd = 0; dd < 128; dd++) {
            float v = cn[e1][dd];
#pragma unroll
            for (int i = 0; i < 16; i++) acc[i] += v * cn[g2*16 + i][dd];
        }
        __syncthreads();
    }
#pragma unroll
    for (int i = 0; i < 16; i++) atomicAdd(&g_H[e1 * NE + g2*16 + i], acc[i]);
}

// ---------------- loss partial sums ----------------
__global__ void k_loss() {
    __shared__ float red[64];
    __shared__ float xmw[CC];
    int n = blockIdx.x, e = threadIdx.x;
#pragma unroll
    for (int l = 0; l < 4; l++)
        xmw[e + l*64] = g_XM[(size_t)n * CC + e + l*64] + g_Wtb[e + l*64];
    __syncthreads();
    float P = 0.f;
    for (int c = 0; c < CC; c++) P += xmw[c] * g_A[e * CC + c];
    float r = g_resp[(size_t)n * NE + e];
    float dotne = g_xG[(size_t)n * NE + e] + g_bc[e];
    float cross = r * (DECAYv * dotne + GAMv * (P + g_s[e] * (g_xWtb[n] + g_bb)));
    float he = 0.f;
    for (int e2 = 0; e2 < NE; e2++) he += g_resp[(size_t)n * NE + e2] * g_H[e * NE + e2];
    float quad = r * he;

    red[e] = cross; __syncthreads();
    for (int s = 32; s >= 1; s >>= 1) { if (e < s) red[e] += red[e + s]; __syncthreads(); }
    float crs = red[0]; __syncthreads();
    red[e] = quad; __syncthreads();
    for (int s = 32; s >= 1; s >>= 1) { if (e < s) red[e] += red[e + s]; __syncthreads(); }
    float qd = red[0];
    if (e == 0) {
        atomicAdd(&g_acc[0], g_qnorm[n]);
        atomicAdd(&g_acc[1], crs);
        atomicAdd(&g_acc[2], qd);
    }
}

// ---------------- out[n,i] = sum_e r * sum_k Cnew[e,i*C+k]*y[k] + pwB ----------------
__global__ void k_out(float* __restrict__ out, const float* __restrict__ pwB) {
    __shared__ float ys[CC];
    __shared__ float rr[NE];
    __shared__ int   ai[NE];
    __shared__ int   acnt;
    __shared__ float os[ROUT];
    int n = blockIdx.x;
    int tid = threadIdx.x;
    ys[tid] = g_Y[(size_t)n * CC + tid];
    if (tid < NE) rr[tid] = g_resp[(size_t)n * NE + tid];
    __syncthreads();
    if (tid == 0) {
        int c = 0;
        for (int e = 0; e < NE; e++) if (rr[e] > 1e-12f) ai[c++] = e;
        acnt = c;
    }
    __syncthreads();
    int warp = tid >> 5, lane = tid & 31;
    float acc[32];
#pragma unroll
    for (int it = 0; it < 32; it++) acc[it] = 0.f;
    int cnt = acnt;
    for (int a = 0; a < cnt; a++) {
        int e = ai[a];
        float r = rr[e];
        const float* crow = g_Cnew + (size_t)e * DD;
#pragma unroll
        for (int it = 0; it < 32; it++) {
            int i = it * 8 + warp;
            const float* p = crow + i * CC + lane;
            float s = 0.f;
#pragma unroll
            for (int m = 0; m < 8; m++) s += p[m * 32] * ys[lane + m * 32];
#pragma unroll
            for (int o = 16; o >= 1; o >>= 1) s += __shfl_xor_sync(0xffffffffu, s, o);
            acc[it] += r * s;
        }
    }
#pragma unroll
    for (int it = 0; it < 32; it++)
        if (lane == 0) os[it * 8 + warp] = acc[it];
    __syncthreads();
    out[(size_t)n * ROUT + tid] = os[tid] + pwB[tid];
}

// ---------------- final loss ----------------
__global__ void k_final(float* __restrict__ out, int out_size) {
    float loss = COMMITv * (g_acc[0] - 2.f * g_acc[1] + g_acc[2]) / ((float)NN * (float)DD);
    for (int i = NN * ROUT + threadIdx.x; i < out_size; i += blockDim.x) out[i] = loss;
}

extern "C" void kernel_launch(void* const* d_in, const int* in_sizes, int n_in,
                              void* d_out, int out_size) {
    const float* x     = (const float*)d_in[0];
    const float* u     = (const float*)d_in[1];
    const float* W     = (const float*)d_in[2];
    const float* bvec  = (const float*)d_in[3];
    const float* pw1   = (const float*)d_in[4];
    const float* pwB   = (const float*)d_in[5];
    const float* cents = (const float*)d_in[6];
    float* out = (float*)d_out;

    k_zero<<<256, 256>>>();
    k_gram<<<dim3(4, 4, 32), 256>>>(W);
    k_centW<<<128, 256>>>(W, cents, bvec);
    k_pw1T<<<CC, CC>>>(pw1);
    k_xsmall<<<256, 256>>>(x);
    k_resp<<<NN, 64>>>(u);
    k_A<<<64, 256>>>(x);
    k_cnew<<<1024, 256>>>(W, cents, bvec);
    k_H<<<128, 256>>>();
    k_loss<<<NN, 64>>>();
    k_out<<<NN, 256>>>(out, pwB);
    if (out_size > NN * ROUT) k_final<<<1, 64>>>(out, out_size);
}